// round 7
// baseline (speedup 1.0000x reference)
#include <cuda_runtime.h>
#include <cstdint>

#define TB 4096
#define CB 1024
#define HB 64

// scratch for projected K/Q/V: [B*T, H] each = 4 MiB each
__device__ float g_q[4 * TB * HB];
__device__ float g_k[4 * TB * HB];
__device__ float g_v[4 * TB * HB];

// ---------------------------------------------------------------------------
// helpers: tf32 convert + m16n8k8 tf32 mma
// ---------------------------------------------------------------------------
__device__ __forceinline__ uint32_t f2tf(float f) {
    uint32_t u;
    asm("cvt.rna.tf32.f32 %0, %1;" : "=r"(u) : "f"(f));
    return u;
}

__device__ __forceinline__ void mma8(float* c, const uint32_t* a,
                                     uint32_t b0, uint32_t b1) {
    asm volatile(
        "mma.sync.aligned.m16n8k8.row.col.f32.tf32.tf32.f32 "
        "{%0,%1,%2,%3}, {%4,%5,%6,%7}, {%8,%9}, {%0,%1,%2,%3};"
        : "+f"(c[0]), "+f"(c[1]), "+f"(c[2]), "+f"(c[3])
        : "r"(a[0]), "r"(a[1]), "r"(a[2]), "r"(a[3]), "r"(b0), "r"(b1));
}

// ---------------------------------------------------------------------------
// Kernel 1: fused QKV projection on tensor cores (tf32). Unchanged from R5.
// ---------------------------------------------------------------------------
#define XS_STR 36
#define WS_STR 200

__global__ __launch_bounds__(256) void qkv_kernel(
    const float* __restrict__ x,
    const float* __restrict__ Wk, const float* __restrict__ bk,
    const float* __restrict__ Wq, const float* __restrict__ bq,
    const float* __restrict__ Wv, const float* __restrict__ bv)
{
    __shared__ uint32_t xs[64 * XS_STR];   // x tile [row][k] tf32
    __shared__ uint32_t ws[32 * WS_STR];   // W tile [k][3*64 cols] tf32

    const int tid  = threadIdx.x;
    const int lane = tid & 31;
    const int wid  = tid >> 5;
    const int wr   = wid >> 1;        // 0..3
    const int wc   = wid & 1;         // 0..1
    const int g    = lane >> 2;       // 0..7
    const int tig  = lane & 3;        // 0..3
    const long row0 = (long)blockIdx.x * 64;

    float acc[12][4];
#pragma unroll
    for (int nt = 0; nt < 12; nt++)
#pragma unroll
        for (int c = 0; c < 4; c++) acc[nt][c] = 0.f;

    float4 px[2], pw[6];

#define QKV_LOAD(k0_)                                                        \
    {                                                                        \
        _Pragma("unroll")                                                    \
        for (int i = 0; i < 2; i++) {                                        \
            int f = tid + 256 * i;                                           \
            int r = f >> 3, c = (f & 7) * 4;                                 \
            px[i] = *(const float4*)&x[(row0 + r) * CB + (k0_) + c];         \
        }                                                                    \
        _Pragma("unroll")                                                    \
        for (int i = 0; i < 6; i++) {                                        \
            int f = tid + 256 * i;                                           \
            int m = f >> 9, kk = (f >> 4) & 31, c = (f & 15) * 4;            \
            const float* wp = (m == 0) ? Wk : ((m == 1) ? Wq : Wv);          \
            pw[i] = *(const float4*)&wp[(long)((k0_) + kk) * HB + c];        \
        }                                                                    \
    }

    QKV_LOAD(0);

    for (int k0 = 0; k0 < CB; k0 += 32) {
        __syncthreads();
#pragma unroll
        for (int i = 0; i < 2; i++) {
            int f = tid + 256 * i;
            int r = f >> 3, c = (f & 7) * 4;
            *(uint4*)&xs[r * XS_STR + c] =
                make_uint4(f2tf(px[i].x), f2tf(px[i].y),
                           f2tf(px[i].z), f2tf(px[i].w));
        }
#pragma unroll
        for (int i = 0; i < 6; i++) {
            int f = tid + 256 * i;
            int m = f >> 9, kk = (f >> 4) & 31, c = (f & 15) * 4;
            *(uint4*)&ws[kk * WS_STR + m * 64 + c] =
                make_uint4(f2tf(pw[i].x), f2tf(pw[i].y),
                           f2tf(pw[i].z), f2tf(pw[i].w));
        }
        __syncthreads();

        if (k0 + 32 < CB) QKV_LOAD(k0 + 32);

        const int r0 = 16 * wr + g;
#pragma unroll
        for (int kk8 = 0; kk8 < 4; kk8++) {
            uint32_t a[4];
            a[0] = xs[r0 * XS_STR + 8 * kk8 + tig];
            a[1] = xs[(r0 + 8) * XS_STR + 8 * kk8 + tig];
            a[2] = xs[r0 * XS_STR + 8 * kk8 + tig + 4];
            a[3] = xs[(r0 + 8) * XS_STR + 8 * kk8 + tig + 4];
            const uint32_t* w0 = &ws[(8 * kk8 + tig) * WS_STR + 96 * wc];
            const uint32_t* w1 = &ws[(8 * kk8 + tig + 4) * WS_STR + 96 * wc];
#pragma unroll
            for (int nt = 0; nt < 12; nt++)
                mma8(acc[nt], a, w0[8 * nt + g], w1[8 * nt + g]);
        }
    }

    const int r0 = 16 * wr + g;
#pragma unroll
    for (int nt = 0; nt < 12; nt++) {
        int gcol = 96 * wc + 8 * nt + 2 * tig;
        int m = gcol >> 6, lc = gcol & 63;
        const float* bp = (m == 0) ? bk : ((m == 1) ? bq : bv);
        float* op = (m == 0) ? g_k : ((m == 1) ? g_q : g_v);
        float b0 = bp[lc], b1 = bp[lc + 1];
        float* o = op + (row0 + r0) * HB + lc;
        *(float2*)o = make_float2(acc[nt][0] + b0, acc[nt][1] + b1);
        *(float2*)(o + 8 * HB) = make_float2(acc[nt][2] + b0, acc[nt][3] + b1);
    }
}

// ---------------------------------------------------------------------------
// Kernel 2: causal flash attention, tf32 mma, occupancy-2 design.
// Q tiles of 32 rows -> 128 row tiles per batch; block p handles row tiles
// {p, 127-p}: exactly 65 inner 64-key steps for every p -> balanced.
// Grid (64,4) = 256 blocks; __launch_bounds__(256,2) -> 2 blocks/SM.
// 8 warps in 2x4: warp = (wr rows 16*wr.., wc cols 16*wc..), tile 16x16.
// ---------------------------------------------------------------------------
#define KS_STR 68
#define VS_STR 72
#define PS_STR 68
#define KS_OFF 0
#define VS_OFF (64 * KS_STR)
#define PS_OFF (VS_OFF + 64 * VS_STR)
#define RM_OFF (PS_OFF + 32 * PS_STR)
#define RS_OFF (RM_OFF + 128)
#define ATTN_SMEM ((RS_OFF + 128) * 4)

__global__ __launch_bounds__(256, 2) void attn_kernel(float* __restrict__ out)
{
    extern __shared__ uint32_t sm[];
    uint32_t* ks = sm + KS_OFF;     // [key][h]   tf32, stride 68
    uint32_t* vs = sm + VS_OFF;     // [key][h]   tf32, stride 72
    uint32_t* ps = sm + PS_OFF;     // [row][key] tf32, stride 68 (32 rows)
    float* redm = (float*)(sm + RM_OFF);   // [4][32] partial row max
    float* reds = (float*)(sm + RS_OFF);   // [4][32] partial row sum

    const int tid  = threadIdx.x;
    const int lane = tid & 31;
    const int wid  = tid >> 5;
    const int wr   = wid >> 2;         // 0..1  (row group)
    const int wc   = wid & 3;          // 0..3  (col group)
    const int g    = lane >> 2;        // 0..7
    const int tig  = lane & 3;         // 0..3

    const int b = blockIdx.y;
    const int p = blockIdx.x;
    const long base = (long)b * TB * HB;
    const float scale = 0.125f;

    const int lr0 = 16 * wr + g;       // local row in 0..31
    const int lr1 = lr0 + 8;

    float4 pkr[4], pvr[4];             // prefetch regs for next K/V tile

#define ATTN_LOAD(jt_)                                                       \
    {                                                                        \
        const float* kp = g_k + base + (long)((jt_) * 64) * HB;              \
        const float* vp = g_v + base + (long)((jt_) * 64) * HB;              \
        _Pragma("unroll")                                                    \
        for (int i = 0; i < 4; i++) {                                        \
            int f = tid + 256 * i;                                           \
            int r = f >> 4, c = (f & 15) * 4;                                \
            pkr[i] = *(const float4*)&kp[r * HB + c];                        \
            pvr[i] = *(const float4*)&vp[r * HB + c];                        \
        }                                                                    \
    }

#pragma unroll 1
    for (int half = 0; half < 2; half++) {
        const int t = half ? (127 - p) : p;      // 32-row Q tile index
        const int jtmax = t >> 1;                // last 64-key tile

        // ---- Q fragments for this 32-row tile ----
        uint32_t aq[8][4];
        {
            const float* qp = g_q + base + (long)t * 32 * HB;
#pragma unroll
            for (int k = 0; k < 8; k++) {
                int c0 = k * 8 + tig;
                aq[k][0] = f2tf(qp[lr0 * HB + c0]);
                aq[k][1] = f2tf(qp[lr1 * HB + c0]);
                aq[k][2] = f2tf(qp[lr0 * HB + c0 + 4]);
                aq[k][3] = f2tf(qp[lr1 * HB + c0 + 4]);
            }
        }

        float m0 = -1e30f, m1 = -1e30f, l0 = 0.f, l1 = 0.f;
        float acc[2][4];
#pragma unroll
        for (int nt = 0; nt < 2; nt++)
#pragma unroll
            for (int c = 0; c < 4; c++) acc[nt][c] = 0.f;

        ATTN_LOAD(0);

        for (int jt = 0; jt <= jtmax; jt++) {
            __syncthreads();   // prior reads of ks/vs complete
            // ---- commit prefetched K,V tile (fp32 -> tf32) ----
#pragma unroll
            for (int i = 0; i < 4; i++) {
                int f = tid + 256 * i;
                int r = f >> 4, c = (f & 15) * 4;
                *(uint4*)&ks[r * KS_STR + c] =
                    make_uint4(f2tf(pkr[i].x), f2tf(pkr[i].y),
                               f2tf(pkr[i].z), f2tf(pkr[i].w));
                *(uint4*)&vs[r * VS_STR + c] =
                    make_uint4(f2tf(pvr[i].x), f2tf(pvr[i].y),
                               f2tf(pvr[i].z), f2tf(pvr[i].w));
            }
            __syncthreads();

            if (jt < jtmax) ATTN_LOAD(jt + 1);

            // ---- S = Q K^T : warp computes 16x16 via 2 n-tiles x 8 k ----
            float sfr[2][4];
#pragma unroll
            for (int nt = 0; nt < 2; nt++)
#pragma unroll
                for (int c = 0; c < 4; c++) sfr[nt][c] = 0.f;

#pragma unroll
            for (int nt = 0; nt < 2; nt++) {
                const uint32_t* krow = &ks[(16 * wc + 8 * nt + g) * KS_STR];
#pragma unroll
                for (int k = 0; k < 8; k++) {
                    uint32_t b0 = krow[8 * k + tig];
                    uint32_t b1 = krow[8 * k + tig + 4];
                    mma8(sfr[nt], aq[k], b0, b1);
                }
            }

            // ---- scale + causal mask (last tile only) ----
            if (jt == jtmax) {
                const int rowoff = t * 32 - jtmax * 64;   // 0 or 32
#pragma unroll
                for (int nt = 0; nt < 2; nt++) {
                    int c0 = 16 * wc + 8 * nt + 2 * tig;
#pragma unroll
                    for (int c = 0; c < 4; c++) {
                        int lc = c0 + (c & 1);
                        int lr = ((c < 2) ? lr0 : lr1) + rowoff;
                        sfr[nt][c] = (lc > lr) ? -1e30f : sfr[nt][c] * scale;
                    }
                }
            } else {
#pragma unroll
                for (int nt = 0; nt < 2; nt++)
#pragma unroll
                    for (int c = 0; c < 4; c++) sfr[nt][c] *= scale;
            }

            // ---- partial row max (this warp's 16 cols) ----
            float pm0 = fmaxf(fmaxf(sfr[0][0], sfr[0][1]),
                              fmaxf(sfr[1][0], sfr[1][1]));
            float pm1 = fmaxf(fmaxf(sfr[0][2], sfr[0][3]),
                              fmaxf(sfr[1][2], sfr[1][3]));
            pm0 = fmaxf(pm0, __shfl_xor_sync(0xffffffffu, pm0, 1));
            pm0 = fmaxf(pm0, __shfl_xor_sync(0xffffffffu, pm0, 2));
            pm1 = fmaxf(pm1, __shfl_xor_sync(0xffffffffu, pm1, 1));
            pm1 = fmaxf(pm1, __shfl_xor_sync(0xffffffffu, pm1, 2));
            if (tig == 0) {
                redm[wc * 32 + lr0] = pm0;
                redm[wc * 32 + lr1] = pm1;
            }
            __syncthreads();

            // ---- combine max across 4 col groups; exp; stage P; rescale ---
            float mn0 = fmaxf(fmaxf(redm[lr0], redm[32 + lr0]),
                              fmaxf(redm[64 + lr0], redm[96 + lr0]));
            float mn1 = fmaxf(fmaxf(redm[lr1], redm[32 + lr1]),
                              fmaxf(redm[64 + lr1], redm[96 + lr1]));
            mn0 = fmaxf(m0, mn0);
            mn1 = fmaxf(m1, mn1);
            float al0 = __expf(m0 - mn0);
            float al1 = __expf(m1 - mn1);
            m0 = mn0; m1 = mn1;

            float s0 = 0.f, s1 = 0.f;
#pragma unroll
            for (int nt = 0; nt < 2; nt++) {
                float e0 = __expf(sfr[nt][0] - mn0);
                float e1 = __expf(sfr[nt][1] - mn0);
                float e2 = __expf(sfr[nt][2] - mn1);
                float e3 = __expf(sfr[nt][3] - mn1);
                s0 += e0 + e1;
                s1 += e2 + e3;
                int col = 16 * wc + 8 * nt + 2 * tig;
                *(uint2*)&ps[lr0 * PS_STR + col] = make_uint2(f2tf(e0), f2tf(e1));
                *(uint2*)&ps[lr1 * PS_STR + col] = make_uint2(f2tf(e2), f2tf(e3));
                acc[nt][0] *= al0; acc[nt][1] *= al0;
                acc[nt][2] *= al1; acc[nt][3] *= al1;
            }
            s0 += __shfl_xor_sync(0xffffffffu, s0, 1);
            s0 += __shfl_xor_sync(0xffffffffu, s0, 2);
            s1 += __shfl_xor_sync(0xffffffffu, s1, 1);
            s1 += __shfl_xor_sync(0xffffffffu, s1, 2);
            if (tig == 0) {
                reds[wc * 32 + lr0] = s0;
                reds[wc * 32 + lr1] = s1;
            }
            __syncthreads();

            l0 = l0 * al0 + (reds[lr0] + reds[32 + lr0]) +
                            (reds[64 + lr0] + reds[96 + lr0]);
            l1 = l1 * al1 + (reds[lr1] + reds[32 + lr1]) +
                            (reds[64 + lr1] + reds[96 + lr1]);

            // ---- O += P V : 16x16 per warp, 2 n-tiles x 8 k ----
#pragma unroll
            for (int k = 0; k < 8; k++) {
                uint32_t ap[4];
                ap[0] = ps[lr0 * PS_STR + 8 * k + tig];
                ap[1] = ps[lr1 * PS_STR + 8 * k + tig];
                ap[2] = ps[lr0 * PS_STR + 8 * k + tig + 4];
                ap[3] = ps[lr1 * PS_STR + 8 * k + tig + 4];
                const uint32_t* v0 = &vs[(8 * k + tig) * VS_STR + 16 * wc];
                const uint32_t* v1 = &vs[(8 * k + tig + 4) * VS_STR + 16 * wc];
#pragma unroll
                for (int nt = 0; nt < 2; nt++)
                    mma8(acc[nt], ap, v0[8 * nt + g], v1[8 * nt + g]);
            }
        }

        // ---- normalize + write ----
        float inv0 = 1.f / l0;
        float inv1 = 1.f / l1;
        float* op = out + base + (long)t * 32 * HB;
#pragma unroll
        for (int nt = 0; nt < 2; nt++) {
            int col = 16 * wc + 8 * nt + 2 * tig;
            *(float2*)&op[lr0 * HB + col] =
                make_float2(acc[nt][0] * inv0, acc[nt][1] * inv0);
            *(float2*)&op[lr1 * HB + col] =
                make_float2(acc[nt][2] * inv1, acc[nt][3] * inv1);
        }
    }
}

extern "C" void kernel_launch(void* const* d_in, const int* in_sizes, int n_in,
                              void* d_out, int out_size)
{
    const float* x  = (const float*)d_in[0];
    const float* Wk = (const float*)d_in[1];
    const float* bk = (const float*)d_in[2];
    const float* Wq = (const float*)d_in[3];
    const float* bq = (const float*)d_in[4];
    const float* Wv = (const float*)d_in[5];
    const float* bv = (const float*)d_in[6];
    float* out = (float*)d_out;

    (void)in_sizes; (void)n_in; (void)out_size;

    static bool attr_done = false;
    if (!attr_done) {
        cudaFuncSetAttribute(attn_kernel,
                             cudaFuncAttributeMaxDynamicSharedMemorySize,
                             ATTN_SMEM);
        attr_done = true;
    }

    qkv_kernel<<<256, 256>>>(x, Wk, bk, Wq, bq, Wv, bv);
    attn_kernel<<<dim3(64, 4), 256, ATTN_SMEM>>>(out);
}

// round 8
// speedup vs baseline: 1.1440x; 1.1440x over previous
#include <cuda_runtime.h>
#include <cstdint>

#define TB 4096
#define CB 1024
#define HB 64

// scratch for projected K/Q/V: [B*T, H] each = 4 MiB each
__device__ float g_q[4 * TB * HB];
__device__ float g_k[4 * TB * HB];
__device__ float g_v[4 * TB * HB];

// ---------------------------------------------------------------------------
// helpers: tf32 convert + m16n8k8 tf32 mma
// ---------------------------------------------------------------------------
__device__ __forceinline__ uint32_t f2tf(float f) {
    uint32_t u;
    asm("cvt.rna.tf32.f32 %0, %1;" : "=r"(u) : "f"(f));
    return u;
}

__device__ __forceinline__ void mma8(float* c, const uint32_t* a,
                                     uint32_t b0, uint32_t b1) {
    asm volatile(
        "mma.sync.aligned.m16n8k8.row.col.f32.tf32.tf32.f32 "
        "{%0,%1,%2,%3}, {%4,%5,%6,%7}, {%8,%9}, {%0,%1,%2,%3};"
        : "+f"(c[0]), "+f"(c[1]), "+f"(c[2]), "+f"(c[3])
        : "r"(a[0]), "r"(a[1]), "r"(a[2]), "r"(a[3]), "r"(b0), "r"(b1));
}

// ---------------------------------------------------------------------------
// Kernel 1: fused QKV projection on tensor cores (tf32). Unchanged.
// ---------------------------------------------------------------------------
#define XS_STR 36
#define WS_STR 200

__global__ __launch_bounds__(256) void qkv_kernel(
    const float* __restrict__ x,
    const float* __restrict__ Wk, const float* __restrict__ bk,
    const float* __restrict__ Wq, const float* __restrict__ bq,
    const float* __restrict__ Wv, const float* __restrict__ bv)
{
    __shared__ uint32_t xs[64 * XS_STR];   // x tile [row][k] tf32
    __shared__ uint32_t ws[32 * WS_STR];   // W tile [k][3*64 cols] tf32

    const int tid  = threadIdx.x;
    const int lane = tid & 31;
    const int wid  = tid >> 5;
    const int wr   = wid >> 1;        // 0..3
    const int wc   = wid & 1;         // 0..1
    const int g    = lane >> 2;       // 0..7
    const int tig  = lane & 3;        // 0..3
    const long row0 = (long)blockIdx.x * 64;

    float acc[12][4];
#pragma unroll
    for (int nt = 0; nt < 12; nt++)
#pragma unroll
        for (int c = 0; c < 4; c++) acc[nt][c] = 0.f;

    float4 px[2], pw[6];

#define QKV_LOAD(k0_)                                                        \
    {                                                                        \
        _Pragma("unroll")                                                    \
        for (int i = 0; i < 2; i++) {                                        \
            int f = tid + 256 * i;                                           \
            int r = f >> 3, c = (f & 7) * 4;                                 \
            px[i] = *(const float4*)&x[(row0 + r) * CB + (k0_) + c];         \
        }                                                                    \
        _Pragma("unroll")                                                    \
        for (int i = 0; i < 6; i++) {                                        \
            int f = tid + 256 * i;                                           \
            int m = f >> 9, kk = (f >> 4) & 31, c = (f & 15) * 4;            \
            const float* wp = (m == 0) ? Wk : ((m == 1) ? Wq : Wv);          \
            pw[i] = *(const float4*)&wp[(long)((k0_) + kk) * HB + c];        \
        }                                                                    \
    }

    QKV_LOAD(0);

    for (int k0 = 0; k0 < CB; k0 += 32) {
        __syncthreads();
#pragma unroll
        for (int i = 0; i < 2; i++) {
            int f = tid + 256 * i;
            int r = f >> 3, c = (f & 7) * 4;
            *(uint4*)&xs[r * XS_STR + c] =
                make_uint4(f2tf(px[i].x), f2tf(px[i].y),
                           f2tf(px[i].z), f2tf(px[i].w));
        }
#pragma unroll
        for (int i = 0; i < 6; i++) {
            int f = tid + 256 * i;
            int m = f >> 9, kk = (f >> 4) & 31, c = (f & 15) * 4;
            *(uint4*)&ws[kk * WS_STR + m * 64 + c] =
                make_uint4(f2tf(pw[i].x), f2tf(pw[i].y),
                           f2tf(pw[i].z), f2tf(pw[i].w));
        }
        __syncthreads();

        if (k0 + 32 < CB) QKV_LOAD(k0 + 32);

        const int r0 = 16 * wr + g;
#pragma unroll
        for (int kk8 = 0; kk8 < 4; kk8++) {
            uint32_t a[4];
            a[0] = xs[r0 * XS_STR + 8 * kk8 + tig];
            a[1] = xs[(r0 + 8) * XS_STR + 8 * kk8 + tig];
            a[2] = xs[r0 * XS_STR + 8 * kk8 + tig + 4];
            a[3] = xs[(r0 + 8) * XS_STR + 8 * kk8 + tig + 4];
            const uint32_t* w0 = &ws[(8 * kk8 + tig) * WS_STR + 96 * wc];
            const uint32_t* w1 = &ws[(8 * kk8 + tig + 4) * WS_STR + 96 * wc];
#pragma unroll
            for (int nt = 0; nt < 12; nt++)
                mma8(acc[nt], a, w0[8 * nt + g], w1[8 * nt + g]);
        }
    }

    const int r0 = 16 * wr + g;
#pragma unroll
    for (int nt = 0; nt < 12; nt++) {
        int gcol = 96 * wc + 8 * nt + 2 * tig;
        int m = gcol >> 6, lc = gcol & 63;
        const float* bp = (m == 0) ? bk : ((m == 1) ? bq : bv);
        float* op = (m == 0) ? g_k : ((m == 1) ? g_q : g_v);
        float b0 = bp[lc], b1 = bp[lc + 1];
        float* o = op + (row0 + r0) * HB + lc;
        *(float2*)o = make_float2(acc[nt][0] + b0, acc[nt][1] + b1);
        *(float2*)(o + 8 * HB) = make_float2(acc[nt][2] + b0, acc[nt][3] + b1);
    }
}

// ---------------------------------------------------------------------------
// Kernel 2: causal flash attention, tf32 mma, 64x64 tiles (R5 tiling),
// fixed-shift softmax (no running max), ping-pong K/V buffers (1 full
// barrier per tile), permuted K/P smem layouts for LDS.128 fragment loads.
// Grid (32,4); 8 warps in 4x2; block p handles row tiles {p, 63-p} = 65
// inner tiles each (balanced).
// perm(c) = 8*(c&7) + (c>>3): head-dim (K) / key-dim (P) permutation so
// that the 8 k-step fragment words become contiguous.
// ---------------------------------------------------------------------------
#define KS_STR 68
#define VS_STR 72
#define PS_STR 68
#define KS0_OFF 0
#define KS1_OFF (64 * KS_STR)
#define VS0_OFF (2 * 64 * KS_STR)
#define VS1_OFF (VS0_OFF + 64 * VS_STR)
#define PS_OFF  (VS0_OFF + 2 * 64 * VS_STR)
#define RED_OFF (PS_OFF + 64 * PS_STR)
#define ATTN_SMEM ((RED_OFF + 128) * 4)

__global__ __launch_bounds__(256) void attn_kernel(float* __restrict__ out)
{
    extern __shared__ uint32_t sm[];
    uint32_t* ps = sm + PS_OFF;            // [row][perm(key)] tf32
    float* reds = (float*)(sm + RED_OFF);  // [2][64] partial row sums

    const int tid  = threadIdx.x;
    const int lane = tid & 31;
    const int wid  = tid >> 5;
    const int wr   = wid >> 1;         // 0..3 (row group)
    const int wc   = wid & 1;          // 0..1 (col group)
    const int g    = lane >> 2;        // 0..7
    const int tig  = lane & 3;         // 0..3

    const int b = blockIdx.y;
    const int p = blockIdx.x;
    const long base = (long)b * TB * HB;
    // scale * log2(e): QK logits come out in log2 domain -> EX2 directly.
    const float QSC = 0.125f * 1.44269504088896f;

    const int lr0 = 16 * wr + g;
    const int lr1 = lr0 + 8;

    float4 pkr[4], pvr[4];             // prefetch regs for next K/V tile

#define ATTN_LOAD(jt_)                                                       \
    {                                                                        \
        const float* kp = g_k + base + (long)((jt_) * 64) * HB;              \
        const float* vp = g_v + base + (long)((jt_) * 64) * HB;              \
        _Pragma("unroll")                                                    \
        for (int i = 0; i < 4; i++) {                                        \
            int f = tid + 256 * i;                                           \
            int r = f >> 4, c = (f & 15) * 4;                                \
            pkr[i] = *(const float4*)&kp[r * HB + c];                        \
            pvr[i] = *(const float4*)&vp[r * HB + c];                        \
        }                                                                    \
    }

// commit prefetch regs into buffer bi (K permuted, V plain)
#define ATTN_COMMIT(bi_)                                                     \
    {                                                                        \
        uint32_t* kd = sm + ((bi_) ? KS1_OFF : KS0_OFF);                     \
        uint32_t* vd = sm + ((bi_) ? VS1_OFF : VS0_OFF);                     \
        _Pragma("unroll")                                                    \
        for (int i = 0; i < 4; i++) {                                        \
            int f = tid + 256 * i;                                           \
            int r = f >> 4;                                                  \
            int pb = 32 * (f & 1) + ((f & 15) >> 1);                         \
            kd[r * KS_STR + pb +  0] = f2tf(pkr[i].x);                       \
            kd[r * KS_STR + pb +  8] = f2tf(pkr[i].y);                       \
            kd[r * KS_STR + pb + 16] = f2tf(pkr[i].z);                       \
            kd[r * KS_STR + pb + 24] = f2tf(pkr[i].w);                       \
            *(uint4*)&vd[r * VS_STR + (f & 15) * 4] =                        \
                make_uint4(f2tf(pvr[i].x), f2tf(pvr[i].y),                   \
                           f2tf(pvr[i].z), f2tf(pvr[i].w));                  \
        }                                                                    \
    }

#pragma unroll 1
    for (int half = 0; half < 2; half++) {
        const int it = half ? (63 - p) : p;   // 64-row Q tile index
        const int jtmax = it;

        // ---- Q fragments, pre-scaled by scale*log2e ----
        uint32_t aq[8][4];
        {
            const float* qp = g_q + base + (long)(it * 64) * HB;
#pragma unroll
            for (int k = 0; k < 8; k++) {
                int c0 = k * 8 + tig;
                aq[k][0] = f2tf(qp[lr0 * HB + c0] * QSC);
                aq[k][1] = f2tf(qp[lr1 * HB + c0] * QSC);
                aq[k][2] = f2tf(qp[lr0 * HB + c0 + 4] * QSC);
                aq[k][3] = f2tf(qp[lr1 * HB + c0 + 4] * QSC);
            }
        }

        float l0 = 0.f, l1 = 0.f;
        float acc[4][4];
#pragma unroll
        for (int nt = 0; nt < 4; nt++)
#pragma unroll
            for (int c = 0; c < 4; c++) acc[nt][c] = 0.f;

        // prologue: tile0 -> buf0; tile1 -> regs
        ATTN_LOAD(0);
        __syncthreads();          // protect buffers vs previous half's reads
        ATTN_COMMIT(0);
        if (jtmax >= 1) ATTN_LOAD(1);

        for (int jt = 0; jt <= jtmax; jt++) {
            const int cur = jt & 1;
            __syncthreads();      // buf[cur] visible; buf[1-cur] free
            if (jt < jtmax) {
                ATTN_COMMIT(1 - cur);
                if (jt + 1 < jtmax) ATTN_LOAD(jt + 2);
            }
            const uint32_t* ksb = sm + (cur ? KS1_OFF : KS0_OFF);
            const uint32_t* vsb = sm + (cur ? VS1_OFF : VS0_OFF);

            // ---- S' = (Q*QSC) K^T : 16x32 per warp, log2-domain logits ---
            float sfr[4][4];
#pragma unroll
            for (int nt = 0; nt < 4; nt++)
#pragma unroll
                for (int c = 0; c < 4; c++) sfr[nt][c] = 0.f;

#pragma unroll
            for (int nt = 0; nt < 4; nt++) {
                const uint32_t* kr = &ksb[(32 * wc + 8 * nt + g) * KS_STR];
                uint4 b0a = *(const uint4*)&kr[8 * tig];        // b0 k=0..3
                uint4 b0b = *(const uint4*)&kr[8 * tig + 4];    // b0 k=4..7
                uint4 b1a = *(const uint4*)&kr[8 * tig + 32];   // b1 k=0..3
                uint4 b1b = *(const uint4*)&kr[8 * tig + 36];   // b1 k=4..7
                mma8(sfr[nt], aq[0], b0a.x, b1a.x);
                mma8(sfr[nt], aq[1], b0a.y, b1a.y);
                mma8(sfr[nt], aq[2], b0a.z, b1a.z);
                mma8(sfr[nt], aq[3], b0a.w, b1a.w);
                mma8(sfr[nt], aq[4], b0b.x, b1b.x);
                mma8(sfr[nt], aq[5], b0b.y, b1b.y);
                mma8(sfr[nt], aq[6], b0b.z, b1b.z);
                mma8(sfr[nt], aq[7], b0b.w, b1b.w);
            }

            // ---- causal mask (diagonal tile only) ----
            if (jt == jtmax) {
#pragma unroll
                for (int nt = 0; nt < 4; nt++) {
                    int c0 = 32 * wc + 8 * nt + 2 * tig;
#pragma unroll
                    for (int c = 0; c < 4; c++) {
                        int lc = c0 + (c & 1);
                        int lr = (c < 2) ? lr0 : lr1;
                        if (lc > lr) sfr[nt][c] = -1e30f;
                    }
                }
            }

            // ---- p = 2^s' (fixed-shift softmax), stage P permuted -------
#pragma unroll
            for (int nt = 0; nt < 4; nt++) {
                float e0 = exp2f(sfr[nt][0]);
                float e1 = exp2f(sfr[nt][1]);
                float e2 = exp2f(sfr[nt][2]);
                float e3 = exp2f(sfr[nt][3]);
                l0 += e0 + e1;
                l1 += e2 + e3;
                int p0 = 16 * tig + 4 * wc + nt;
                ps[lr0 * PS_STR + p0]     = f2tf(e0);
                ps[lr0 * PS_STR + p0 + 8] = f2tf(e1);
                ps[lr1 * PS_STR + p0]     = f2tf(e2);
                ps[lr1 * PS_STR + p0 + 8] = f2tf(e3);
            }
            // pair barrier: warps (wr,0),(wr,1) share ps rows
            asm volatile("bar.sync %0, 64;" :: "r"(1 + wr));

            // ---- O += P V : 16x32 per warp ----
#pragma unroll
            for (int kh = 0; kh < 2; kh++) {
                int off = 8 * tig + 4 * kh;
                uint4 a00 = *(const uint4*)&ps[lr0 * PS_STR + off];
                uint4 a10 = *(const uint4*)&ps[lr1 * PS_STR + off];
                uint4 a01 = *(const uint4*)&ps[lr0 * PS_STR + off + 32];
                uint4 a11 = *(const uint4*)&ps[lr1 * PS_STR + off + 32];
                uint32_t w00[4] = {a00.x, a00.y, a00.z, a00.w};
                uint32_t w10[4] = {a10.x, a10.y, a10.z, a10.w};
                uint32_t w01[4] = {a01.x, a01.y, a01.z, a01.w};
                uint32_t w11[4] = {a11.x, a11.y, a11.z, a11.w};
#pragma unroll
                for (int kk = 0; kk < 4; kk++) {
                    int k = 4 * kh + kk;
                    uint32_t ap[4] = {w00[kk], w10[kk], w01[kk], w11[kk]};
                    const uint32_t* v0 = &vsb[(8 * k + tig) * VS_STR + 32 * wc];
                    const uint32_t* v1 = &vsb[(8 * k + tig + 4) * VS_STR + 32 * wc];
#pragma unroll
                    for (int nt = 0; nt < 4; nt++)
                        mma8(acc[nt], ap, v0[8 * nt + g], v1[8 * nt + g]);
                }
            }
        }

        // ---- final row-sum reduce + normalize + write ----
        l0 += __shfl_xor_sync(0xffffffffu, l0, 1);
        l0 += __shfl_xor_sync(0xffffffffu, l0, 2);
        l1 += __shfl_xor_sync(0xffffffffu, l1, 1);
        l1 += __shfl_xor_sync(0xffffffffu, l1, 2);
        if (tig == 0) {
            reds[wc * 64 + lr0] = l0;
            reds[wc * 64 + lr1] = l1;
        }
        __syncthreads();
        float inv0 = 1.f / (reds[lr0] + reds[64 + lr0]);
        float inv1 = 1.f / (reds[lr1] + reds[64 + lr1]);

        float* op = out + base + (long)(it * 64) * HB;
#pragma unroll
        for (int nt = 0; nt < 4; nt++) {
            int col = 32 * wc + 8 * nt + 2 * tig;
            *(float2*)&op[lr0 * HB + col] =
                make_float2(acc[nt][0] * inv0, acc[nt][1] * inv0);
            *(float2*)&op[lr1 * HB + col] =
                make_float2(acc[nt][2] * inv1, acc[nt][3] * inv1);
        }
    }
}

extern "C" void kernel_launch(void* const* d_in, const int* in_sizes, int n_in,
                              void* d_out, int out_size)
{
    const float* x  = (const float*)d_in[0];
    const float* Wk = (const float*)d_in[1];
    const float* bk = (const float*)d_in[2];
    const float* Wq = (const float*)d_in[3];
    const float* bq = (const float*)d_in[4];
    const float* Wv = (const float*)d_in[5];
    const float* bv = (const float*)d_in[6];
    float* out = (float*)d_out;

    (void)in_sizes; (void)n_in; (void)out_size;

    static bool attr_done = false;
    if (!attr_done) {
        cudaFuncSetAttribute(attn_kernel,
                             cudaFuncAttributeMaxDynamicSharedMemorySize,
                             ATTN_SMEM);
        attr_done = true;
    }

    qkv_kernel<<<256, 256>>>(x, Wk, bk, Wq, bq, Wv, bv);
    attn_kernel<<<dim3(32, 4), 256, ATTN_SMEM>>>(out);
}

// round 9
// speedup vs baseline: 1.3219x; 1.1554x over previous
#include <cuda_runtime.h>
#include <cstdint>

#define TB 4096
#define CB 1024
#define HB 64

// scratch for projected K/Q/V: [B*T, H] each = 4 MiB each
__device__ float g_q[4 * TB * HB];
__device__ float g_k[4 * TB * HB];
__device__ float g_v[4 * TB * HB];
// split-K partials: [b][it][z][64 rows][64 cols] and [b][it][z][64 rows]
__device__ float g_pacc[4 * 64 * 2 * 64 * 64];
__device__ float g_pl[4 * 64 * 2 * 64];

// ---------------------------------------------------------------------------
// helpers
// ---------------------------------------------------------------------------
__device__ __forceinline__ uint32_t f2tf(float f) {
    uint32_t u;
    asm("cvt.rna.tf32.f32 %0, %1;" : "=r"(u) : "f"(f));
    return u;
}

__device__ __forceinline__ void mma8(float* c, const uint32_t* a,
                                     uint32_t b0, uint32_t b1) {
    asm volatile(
        "mma.sync.aligned.m16n8k8.row.col.f32.tf32.tf32.f32 "
        "{%0,%1,%2,%3}, {%4,%5,%6,%7}, {%8,%9}, {%0,%1,%2,%3};"
        : "+f"(c[0]), "+f"(c[1]), "+f"(c[2]), "+f"(c[3])
        : "r"(a[0]), "r"(a[1]), "r"(a[2]), "r"(a[3]), "r"(b0), "r"(b1));
}

#define CP_ASYNC16(dst_u32, src_ptr)                                         \
    asm volatile("cp.async.cg.shared.global [%0], [%1], 16;"                 \
                 :: "r"(dst_u32), "l"(src_ptr) : "memory")

// ---------------------------------------------------------------------------
// Kernel 1: fused QKV projection on tensor cores (tf32). Unchanged.
// ---------------------------------------------------------------------------
#define XS_STR 36
#define WS_STR 200

__global__ __launch_bounds__(256) void qkv_kernel(
    const float* __restrict__ x,
    const float* __restrict__ Wk, const float* __restrict__ bk,
    const float* __restrict__ Wq, const float* __restrict__ bq,
    const float* __restrict__ Wv, const float* __restrict__ bv)
{
    __shared__ uint32_t xs[64 * XS_STR];   // x tile [row][k] tf32
    __shared__ uint32_t ws[32 * WS_STR];   // W tile [k][3*64 cols] tf32

    const int tid  = threadIdx.x;
    const int lane = tid & 31;
    const int wid  = tid >> 5;
    const int wr   = wid >> 1;
    const int wc   = wid & 1;
    const int g    = lane >> 2;
    const int tig  = lane & 3;
    const long row0 = (long)blockIdx.x * 64;

    float acc[12][4];
#pragma unroll
    for (int nt = 0; nt < 12; nt++)
#pragma unroll
        for (int c = 0; c < 4; c++) acc[nt][c] = 0.f;

    float4 px[2], pw[6];

#define QKV_LOAD(k0_)                                                        \
    {                                                                        \
        _Pragma("unroll")                                                    \
        for (int i = 0; i < 2; i++) {                                        \
            int f = tid + 256 * i;                                           \
            int r = f >> 3, c = (f & 7) * 4;                                 \
            px[i] = *(const float4*)&x[(row0 + r) * CB + (k0_) + c];         \
        }                                                                    \
        _Pragma("unroll")                                                    \
        for (int i = 0; i < 6; i++) {                                        \
            int f = tid + 256 * i;                                           \
            int m = f >> 9, kk = (f >> 4) & 31, c = (f & 15) * 4;            \
            const float* wp = (m == 0) ? Wk : ((m == 1) ? Wq : Wv);          \
            pw[i] = *(const float4*)&wp[(long)((k0_) + kk) * HB + c];        \
        }                                                                    \
    }

    QKV_LOAD(0);

    for (int k0 = 0; k0 < CB; k0 += 32) {
        __syncthreads();
#pragma unroll
        for (int i = 0; i < 2; i++) {
            int f = tid + 256 * i;
            int r = f >> 3, c = (f & 7) * 4;
            *(uint4*)&xs[r * XS_STR + c] =
                make_uint4(f2tf(px[i].x), f2tf(px[i].y),
                           f2tf(px[i].z), f2tf(px[i].w));
        }
#pragma unroll
        for (int i = 0; i < 6; i++) {
            int f = tid + 256 * i;
            int m = f >> 9, kk = (f >> 4) & 31, c = (f & 15) * 4;
            *(uint4*)&ws[kk * WS_STR + m * 64 + c] =
                make_uint4(f2tf(pw[i].x), f2tf(pw[i].y),
                           f2tf(pw[i].z), f2tf(pw[i].w));
        }
        __syncthreads();

        if (k0 + 32 < CB) QKV_LOAD(k0 + 32);

        const int r0 = 16 * wr + g;
#pragma unroll
        for (int kk8 = 0; kk8 < 4; kk8++) {
            uint32_t a[4];
            a[0] = xs[r0 * XS_STR + 8 * kk8 + tig];
            a[1] = xs[(r0 + 8) * XS_STR + 8 * kk8 + tig];
            a[2] = xs[r0 * XS_STR + 8 * kk8 + tig + 4];
            a[3] = xs[(r0 + 8) * XS_STR + 8 * kk8 + tig + 4];
            const uint32_t* w0 = &ws[(8 * kk8 + tig) * WS_STR + 96 * wc];
            const uint32_t* w1 = &ws[(8 * kk8 + tig + 4) * WS_STR + 96 * wc];
#pragma unroll
            for (int nt = 0; nt < 12; nt++)
                mma8(acc[nt], a, w0[8 * nt + g], w1[8 * nt + g]);
        }
    }

    const int r0 = 16 * wr + g;
#pragma unroll
    for (int nt = 0; nt < 12; nt++) {
        int gcol = 96 * wc + 8 * nt + 2 * tig;
        int m = gcol >> 6, lc = gcol & 63;
        const float* bp = (m == 0) ? bk : ((m == 1) ? bq : bv);
        float* op = (m == 0) ? g_k : ((m == 1) ? g_q : g_v);
        float b0 = bp[lc], b1 = bp[lc + 1];
        float* o = op + (row0 + r0) * HB + lc;
        *(float2*)o = make_float2(acc[nt][0] + b0, acc[nt][1] + b1);
        *(float2*)(o + 8 * HB) = make_float2(acc[nt][2] + b0, acc[nt][3] + b1);
    }
}

// ---------------------------------------------------------------------------
// Kernel 2: causal flash attention, tf32 mma, 64x64 tiles, split-K.
// Fixed-shift softmax (partials combine by addition). Grid (32, 4, 2):
// block (p, b, z) handles row tiles {p, 63-p}; for tile it (n=it+1 key
// tiles, h=(n+1)/2): z=0 does [0,h), z=1 does [h,n) -> 32/33 tiles per
// block, perfectly balanced. cp.async ping-pong staging of K/V (raw fp32,
// consumed by mma.tf32 as truncation). 2 blocks/SM.
// ---------------------------------------------------------------------------
#define KS_STR 68
#define VS_STR 72
#define PS_STR 68
#define KS0_OFF 0
#define KS1_OFF (64 * KS_STR)
#define VS0_OFF (2 * 64 * KS_STR)
#define VS1_OFF (VS0_OFF + 64 * VS_STR)
#define PS_OFF  (VS0_OFF + 2 * 64 * VS_STR)
#define RED_OFF (PS_OFF + 64 * PS_STR)
#define ATTN_SMEM ((RED_OFF + 128) * 4)

__global__ __launch_bounds__(256, 2) void attn_kernel()
{
    extern __shared__ uint32_t sm[];
    uint32_t* ps = sm + PS_OFF;            // [row][key] tf32
    float* reds = (float*)(sm + RED_OFF);  // [2][64] partial row sums

    const int tid  = threadIdx.x;
    const int lane = tid & 31;
    const int wid  = tid >> 5;
    const int wr   = wid >> 1;         // 0..3 (row group)
    const int wc   = wid & 1;          // 0..1 (col group)
    const int g    = lane >> 2;        // 0..7
    const int tig  = lane & 3;         // 0..3

    const int b = blockIdx.y;
    const int p = blockIdx.x;
    const int z = blockIdx.z;
    const long base = (long)b * TB * HB;
    const float QSC = 0.125f * 1.44269504088896f;  // scale * log2(e)

    const int lr0 = 16 * wr + g;
    const int lr1 = lr0 + 8;

    const uint32_t ksu[2] = { (uint32_t)__cvta_generic_to_shared(sm + KS0_OFF),
                              (uint32_t)__cvta_generic_to_shared(sm + KS1_OFF) };
    const uint32_t vsu[2] = { (uint32_t)__cvta_generic_to_shared(sm + VS0_OFF),
                              (uint32_t)__cvta_generic_to_shared(sm + VS1_OFF) };

#define ATTN_ISSUE(jt_, bi_)                                                 \
    {                                                                        \
        const float* kp = g_k + base + (long)((jt_) * 64) * HB;              \
        const float* vp = g_v + base + (long)((jt_) * 64) * HB;              \
        _Pragma("unroll")                                                    \
        for (int i = 0; i < 4; i++) {                                        \
            int f = tid + 256 * i;                                           \
            int r = f >> 4, c = (f & 15) * 4;                                \
            CP_ASYNC16(ksu[bi_] + (r * KS_STR + c) * 4, kp + r * HB + c);    \
            CP_ASYNC16(vsu[bi_] + (r * VS_STR + c) * 4, vp + r * HB + c);    \
        }                                                                    \
        asm volatile("cp.async.commit_group;" ::: "memory");                 \
    }

#pragma unroll 1
    for (int half = 0; half < 2; half++) {
        const int it = half ? (63 - p) : p;   // 64-row Q tile index
        const int n  = it + 1;                // total key tiles
        const int h  = (n + 1) >> 1;
        const int j0 = z ? h : 0;
        const int j1 = z ? (n - 1) : (h - 1);
        const int cnt = j1 - j0 + 1;          // may be 0 (z=1, it=0)

        // ---- Q fragments, pre-scaled by scale*log2e ----
        uint32_t aq[8][4];
        {
            const float* qp = g_q + base + (long)(it * 64) * HB;
#pragma unroll
            for (int k = 0; k < 8; k++) {
                int c0 = k * 8 + tig;
                aq[k][0] = f2tf(qp[lr0 * HB + c0] * QSC);
                aq[k][1] = f2tf(qp[lr1 * HB + c0] * QSC);
                aq[k][2] = f2tf(qp[lr0 * HB + c0 + 4] * QSC);
                aq[k][3] = f2tf(qp[lr1 * HB + c0 + 4] * QSC);
            }
        }

        float l0 = 0.f, l1 = 0.f;
        float acc[4][4];
#pragma unroll
        for (int nt = 0; nt < 4; nt++)
#pragma unroll
            for (int c = 0; c < 4; c++) acc[nt][c] = 0.f;

        if (cnt >= 1) ATTN_ISSUE(j0, 0);
        if (cnt >= 2) ATTN_ISSUE(j0 + 1, 1);

        for (int jt = j0; jt <= j1; jt++) {
            const int cur = (jt - j0) & 1;
            if (jt < j1)
                asm volatile("cp.async.wait_group 1;" ::: "memory");
            else
                asm volatile("cp.async.wait_group 0;" ::: "memory");
            __syncthreads();   // tile jt visible to all threads

            const uint32_t* ksb = sm + (cur ? KS1_OFF : KS0_OFF);
            const uint32_t* vsb = sm + (cur ? VS1_OFF : VS0_OFF);

            // ---- S' = (Q*QSC) K^T : 16x32 per warp (log2-domain) ----
            float sfr[4][4];
#pragma unroll
            for (int nt = 0; nt < 4; nt++)
#pragma unroll
                for (int c = 0; c < 4; c++) sfr[nt][c] = 0.f;

#pragma unroll
            for (int nt = 0; nt < 4; nt++) {
                const uint32_t* krow = &ksb[(32 * wc + 8 * nt + g) * KS_STR];
#pragma unroll
                for (int k = 0; k < 8; k++) {
                    uint32_t b0 = krow[8 * k + tig];
                    uint32_t b1 = krow[8 * k + tig + 4];
                    mma8(sfr[nt], aq[k], b0, b1);
                }
            }

            // ---- causal mask (diagonal tile only) ----
            if (jt == it) {
#pragma unroll
                for (int nt = 0; nt < 4; nt++) {
                    int c0 = 32 * wc + 8 * nt + 2 * tig;
#pragma unroll
                    for (int c = 0; c < 4; c++) {
                        int lc = c0 + (c & 1);
                        int lr = (c < 2) ? lr0 : lr1;
                        if (lc > lr) sfr[nt][c] = -1e30f;
                    }
                }
            }

            // ---- p = 2^s' (fixed-shift softmax), stage P ----
#pragma unroll
            for (int nt = 0; nt < 4; nt++) {
                float e0 = exp2f(sfr[nt][0]);
                float e1 = exp2f(sfr[nt][1]);
                float e2 = exp2f(sfr[nt][2]);
                float e3 = exp2f(sfr[nt][3]);
                l0 += e0 + e1;
                l1 += e2 + e3;
                int col = 32 * wc + 8 * nt + 2 * tig;
                *(uint2*)&ps[lr0 * PS_STR + col] = make_uint2(f2tf(e0), f2tf(e1));
                *(uint2*)&ps[lr1 * PS_STR + col] = make_uint2(f2tf(e2), f2tf(e3));
            }
            // pair barrier: warps (wr,0),(wr,1) share ps rows
            asm volatile("bar.sync %0, 64;" :: "r"(1 + wr));

            // ---- O += P V : 16x32 per warp ----
#pragma unroll
            for (int k = 0; k < 8; k++) {
                uint32_t ap[4];
                ap[0] = ps[lr0 * PS_STR + 8 * k + tig];
                ap[1] = ps[lr1 * PS_STR + 8 * k + tig];
                ap[2] = ps[lr0 * PS_STR + 8 * k + tig + 4];
                ap[3] = ps[lr1 * PS_STR + 8 * k + tig + 4];
                const uint32_t* v0 = &vsb[(8 * k + tig) * VS_STR + 32 * wc];
                const uint32_t* v1 = &vsb[(8 * k + tig + 4) * VS_STR + 32 * wc];
#pragma unroll
                for (int nt = 0; nt < 4; nt++)
                    mma8(acc[nt], ap, v0[8 * nt + g], v1[8 * nt + g]);
            }

            __syncthreads();   // all warps done with buf[cur] and ps
            if (jt + 2 <= j1) ATTN_ISSUE(jt + 2, cur);
        }

        // ---- reduce partial row sums; write partials to scratch ----
        l0 += __shfl_xor_sync(0xffffffffu, l0, 1);
        l0 += __shfl_xor_sync(0xffffffffu, l0, 2);
        l1 += __shfl_xor_sync(0xffffffffu, l1, 1);
        l1 += __shfl_xor_sync(0xffffffffu, l1, 2);
        if (tig == 0) {
            reds[wc * 64 + lr0] = l0;
            reds[wc * 64 + lr1] = l1;
        }
        __syncthreads();

        const long pidx = ((long)(b * 64 + it) * 2 + z);
        if (tig == 0 && wc == 0) {
            g_pl[pidx * 64 + lr0] = reds[lr0] + reds[64 + lr0];
            g_pl[pidx * 64 + lr1] = reds[lr1] + reds[64 + lr1];
        }
        float* pa = g_pacc + pidx * 64 * 64;
#pragma unroll
        for (int nt = 0; nt < 4; nt++) {
            int col = 32 * wc + 8 * nt + 2 * tig;
            *(float2*)&pa[lr0 * 64 + col] = make_float2(acc[nt][0], acc[nt][1]);
            *(float2*)&pa[lr1 * 64 + col] = make_float2(acc[nt][2], acc[nt][3]);
        }
        __syncthreads();  // reds reuse safety for next half
    }
}

// ---------------------------------------------------------------------------
// Kernel 3: combine split-K partials.  out = (acc_z0 + acc_z1) / (l_z0+l_z1)
// Grid (64, 4), 256 threads: one block per (it, b) Q tile.
// ---------------------------------------------------------------------------
__global__ __launch_bounds__(256) void combine_kernel(float* __restrict__ out)
{
    const int it = blockIdx.x, b = blockIdx.y;
    const int tid = threadIdx.x;
    const long pidx = (long)(b * 64 + it) * 2;
    const float* pa0 = g_pacc + pidx * 64 * 64;
    const float* pa1 = pa0 + 64 * 64;
    const float* pl0 = g_pl + pidx * 64;
    const float* pl1 = pl0 + 64;

    __shared__ float linv[64];
    if (tid < 64) linv[tid] = 1.f / (pl0[tid] + pl1[tid]);
    __syncthreads();

    float* op = out + ((long)b * TB + (long)it * 64) * HB;
#pragma unroll
    for (int i = 0; i < 4; i++) {
        int f = tid + 256 * i;
        int r = f >> 4, c = (f & 15) * 4;
        float4 a0 = *(const float4*)&pa0[r * 64 + c];
        float4 a1 = *(const float4*)&pa1[r * 64 + c];
        float s = linv[r];
        *(float4*)&op[r * HB + c] =
            make_float4((a0.x + a1.x) * s, (a0.y + a1.y) * s,
                        (a0.z + a1.z) * s, (a0.w + a1.w) * s);
    }
}

extern "C" void kernel_launch(void* const* d_in, const int* in_sizes, int n_in,
                              void* d_out, int out_size)
{
    const float* x  = (const float*)d_in[0];
    const float* Wk = (const float*)d_in[1];
    const float* bk = (const float*)d_in[2];
    const float* Wq = (const float*)d_in[3];
    const float* bq = (const float*)d_in[4];
    const float* Wv = (const float*)d_in[5];
    const float* bv = (const float*)d_in[6];
    float* out = (float*)d_out;

    (void)in_sizes; (void)n_in; (void)out_size;

    static bool attr_done = false;
    if (!attr_done) {
        cudaFuncSetAttribute(attn_kernel,
                             cudaFuncAttributeMaxDynamicSharedMemorySize,
                             ATTN_SMEM);
        attr_done = true;
    }

    qkv_kernel<<<256, 256>>>(x, Wk, bk, Wq, bq, Wv, bv);
    attn_kernel<<<dim3(32, 4, 2), 256, ATTN_SMEM>>>();
    combine_kernel<<<dim3(64, 4), 256>>>(out);
}

// round 11
// speedup vs baseline: 1.3488x; 1.0204x over previous
#include <cuda_runtime.h>
#include <cstdint>

#define TB 4096
#define CB 1024
#define HB 64

// scratch for projected K/Q/V: [B*T, H] each = 4 MiB each
__device__ float g_q[4 * TB * HB];
__device__ float g_k[4 * TB * HB];
__device__ float g_v[4 * TB * HB];
// split-K partials: [b][it][z][64 rows][64 cols] and [b][it][z][64 rows]
__device__ float g_pacc[4 * 64 * 2 * 64 * 64];
__device__ float g_pl[4 * 64 * 2 * 64];

// ---------------------------------------------------------------------------
// helpers
// ---------------------------------------------------------------------------
__device__ __forceinline__ uint32_t f2tf(float f) {
    uint32_t u;
    asm("cvt.rna.tf32.f32 %0, %1;" : "=r"(u) : "f"(f));
    return u;
}

__device__ __forceinline__ void mma8(float* c, const uint32_t* a,
                                     uint32_t b0, uint32_t b1) {
    asm volatile(
        "mma.sync.aligned.m16n8k8.row.col.f32.tf32.tf32.f32 "
        "{%0,%1,%2,%3}, {%4,%5,%6,%7}, {%8,%9}, {%0,%1,%2,%3};"
        : "+f"(c[0]), "+f"(c[1]), "+f"(c[2]), "+f"(c[3])
        : "r"(a[0]), "r"(a[1]), "r"(a[2]), "r"(a[3]), "r"(b0), "r"(b1));
}

#define CP_ASYNC16(dst_u32, src_ptr)                                         \
    asm volatile("cp.async.cg.shared.global [%0], [%1], 16;"                 \
                 :: "r"(dst_u32), "l"(src_ptr) : "memory")

// ---------------------------------------------------------------------------
// Kernel 1: fused QKV projection, tf32 mma, cp.async 3-stage pipeline.
// Raw fp32 staged in smem; cvt.rna applied in registers after LDS (numerics
// identical to staging-time cvt). Grid 256 x 256 thr, 2 blocks/SM.
// 8 warps in 4x2: rows 16*wr.., cols 96*wc.. of the 64x192 output tile.
// NOTE: macro locals are _q-suffixed to avoid capturing caller variables
// (the R9 bug: QKV_ISSUE(c+2,..) captured the macro-internal `c`).
// ---------------------------------------------------------------------------
#define XS_STR 36
#define WS_STR 200
#define QKV_STG (64 * XS_STR + 32 * WS_STR)   // words per stage (8704)
#define QKV_SMEM (3 * QKV_STG * 4)            // 104448 B

__global__ __launch_bounds__(256, 2) void qkv_kernel(
    const float* __restrict__ x,
    const float* __restrict__ Wk, const float* __restrict__ bk,
    const float* __restrict__ Wq, const float* __restrict__ bq,
    const float* __restrict__ Wv, const float* __restrict__ bv)
{
    extern __shared__ float qsm[];

    const int tid  = threadIdx.x;
    const int lane = tid & 31;
    const int wid  = tid >> 5;
    const int wr   = wid >> 1;        // 0..3
    const int wc   = wid & 1;         // 0..1
    const int g    = lane >> 2;       // 0..7
    const int tig  = lane & 3;        // 0..3
    const long row0 = (long)blockIdx.x * 64;

    const uint32_t smu = (uint32_t)__cvta_generic_to_shared(qsm);

    float acc[12][4];
#pragma unroll
    for (int nt = 0; nt < 12; nt++)
#pragma unroll
        for (int c = 0; c < 4; c++) acc[nt][c] = 0.f;

    // issue one 32-k chunk (x: 64x32, W: 3 x 32x64) into stage s
#define QKV_ISSUE(kc_, s_)                                                   \
    {                                                                        \
        const uint32_t xb_q = smu + (s_) * QKV_STG * 4;                      \
        const uint32_t wb_q = xb_q + 64 * XS_STR * 4;                        \
        _Pragma("unroll")                                                    \
        for (int i_q = 0; i_q < 2; i_q++) {                                  \
            int f_q = tid + 256 * i_q;                                       \
            int r_q = f_q >> 3, c_q = (f_q & 7) * 4;                         \
            CP_ASYNC16(xb_q + (r_q * XS_STR + c_q) * 4,                      \
                       &x[(row0 + r_q) * CB + (kc_) * 32 + c_q]);            \
        }                                                                    \
        _Pragma("unroll")                                                    \
        for (int i_q = 0; i_q < 6; i_q++) {                                  \
            int f_q = tid + 256 * i_q;                                       \
            int m_q = f_q >> 9, kk_q = (f_q >> 4) & 31, c_q = (f_q & 15) * 4;\
            const float* wp_q = (m_q == 0) ? Wk : ((m_q == 1) ? Wq : Wv);    \
            CP_ASYNC16(wb_q + (kk_q * WS_STR + m_q * 64 + c_q) * 4,          \
                       &wp_q[(long)((kc_) * 32 + kk_q) * HB + c_q]);         \
        }                                                                    \
        asm volatile("cp.async.commit_group;" ::: "memory");                 \
    }

    QKV_ISSUE(0, 0);
    QKV_ISSUE(1, 1);

    const int r0 = 16 * wr + g;

    for (int ck = 0; ck < 32; ck++) {
        if (ck < 31)
            asm volatile("cp.async.wait_group 1;" ::: "memory");
        else
            asm volatile("cp.async.wait_group 0;" ::: "memory");
        __syncthreads();   // chunk ck ready; buffer of chunk ck-1 free

        if (ck + 2 < 32) QKV_ISSUE(ck + 2, (ck + 2) % 3);

        const float* xb = qsm + (ck % 3) * QKV_STG;
        const float* wb = xb + 64 * XS_STR;

#pragma unroll
        for (int kk8 = 0; kk8 < 4; kk8++) {
            uint32_t a[4];
            a[0] = f2tf(xb[r0 * XS_STR + 8 * kk8 + tig]);
            a[1] = f2tf(xb[(r0 + 8) * XS_STR + 8 * kk8 + tig]);
            a[2] = f2tf(xb[r0 * XS_STR + 8 * kk8 + tig + 4]);
            a[3] = f2tf(xb[(r0 + 8) * XS_STR + 8 * kk8 + tig + 4]);
            const float* w0 = wb + (8 * kk8 + tig) * WS_STR + 96 * wc;
            const float* w1 = wb + (8 * kk8 + tig + 4) * WS_STR + 96 * wc;
#pragma unroll
            for (int nt = 0; nt < 12; nt++)
                mma8(acc[nt], a, f2tf(w0[8 * nt + g]), f2tf(w1[8 * nt + g]));
        }
    }

    // epilogue: add bias, scatter to g_k / g_q / g_v
#pragma unroll
    for (int nt = 0; nt < 12; nt++) {
        int gcol = 96 * wc + 8 * nt + 2 * tig;
        int m = gcol >> 6, lc = gcol & 63;
        const float* bp = (m == 0) ? bk : ((m == 1) ? bq : bv);
        float* op = (m == 0) ? g_k : ((m == 1) ? g_q : g_v);
        float b0 = bp[lc], b1 = bp[lc + 1];
        float* o = op + (row0 + r0) * HB + lc;
        *(float2*)o = make_float2(acc[nt][0] + b0, acc[nt][1] + b1);
        *(float2*)(o + 8 * HB) = make_float2(acc[nt][2] + b0, acc[nt][3] + b1);
    }
}

// ---------------------------------------------------------------------------
// Kernel 2: causal flash attention, tf32 mma, 64x64 tiles, split-K.
// Grid (32, 4, 2); fixed-shift softmax; cp.async ping-pong K/V staging
// (raw fp32 -> tf32 truncation in mma); 2 blocks/SM. Same as R8 (passing),
// with macro locals renamed for hygiene.
// ---------------------------------------------------------------------------
#define KS_STR 68
#define VS_STR 72
#define PS_STR 68
#define KS0_OFF 0
#define KS1_OFF (64 * KS_STR)
#define VS0_OFF (2 * 64 * KS_STR)
#define VS1_OFF (VS0_OFF + 64 * VS_STR)
#define PS_OFF  (VS0_OFF + 2 * 64 * VS_STR)
#define RED_OFF (PS_OFF + 64 * PS_STR)
#define ATTN_SMEM ((RED_OFF + 128) * 4)

__global__ __launch_bounds__(256, 2) void attn_kernel()
{
    extern __shared__ uint32_t sm[];
    uint32_t* ps = sm + PS_OFF;            // [row][key] tf32
    float* reds = (float*)(sm + RED_OFF);  // [2][64] partial row sums

    const int tid  = threadIdx.x;
    const int lane = tid & 31;
    const int wid  = tid >> 5;
    const int wr   = wid >> 1;         // 0..3 (row group)
    const int wc   = wid & 1;          // 0..1 (col group)
    const int g    = lane >> 2;        // 0..7
    const int tig  = lane & 3;         // 0..3

    const int b = blockIdx.y;
    const int p = blockIdx.x;
    const int z = blockIdx.z;
    const long base = (long)b * TB * HB;
    const float QSC = 0.125f * 1.44269504088896f;  // scale * log2(e)

    const int lr0 = 16 * wr + g;
    const int lr1 = lr0 + 8;

    const uint32_t ksu[2] = { (uint32_t)__cvta_generic_to_shared(sm + KS0_OFF),
                              (uint32_t)__cvta_generic_to_shared(sm + KS1_OFF) };
    const uint32_t vsu[2] = { (uint32_t)__cvta_generic_to_shared(sm + VS0_OFF),
                              (uint32_t)__cvta_generic_to_shared(sm + VS1_OFF) };

#define ATTN_ISSUE(jt_, bi_)                                                 \
    {                                                                        \
        const float* kp_a = g_k + base + (long)((jt_) * 64) * HB;            \
        const float* vp_a = g_v + base + (long)((jt_) * 64) * HB;            \
        _Pragma("unroll")                                                    \
        for (int i_a = 0; i_a < 4; i_a++) {                                  \
            int f_a = tid + 256 * i_a;                                       \
            int r_a = f_a >> 4, c_a = (f_a & 15) * 4;                        \
            CP_ASYNC16(ksu[bi_] + (r_a * KS_STR + c_a) * 4,                  \
                       kp_a + r_a * HB + c_a);                               \
            CP_ASYNC16(vsu[bi_] + (r_a * VS_STR + c_a) * 4,                  \
                       vp_a + r_a * HB + c_a);                               \
        }                                                                    \
        asm volatile("cp.async.commit_group;" ::: "memory");                 \
    }

#pragma unroll 1
    for (int half = 0; half < 2; half++) {
        const int it = half ? (63 - p) : p;   // 64-row Q tile index
        const int n  = it + 1;                // total key tiles
        const int h  = (n + 1) >> 1;
        const int j0 = z ? h : 0;
        const int j1 = z ? (n - 1) : (h - 1);
        const int cnt = j1 - j0 + 1;          // may be 0 (z=1, it=0)

        // ---- Q fragments, pre-scaled by scale*log2e ----
        uint32_t aq[8][4];
        {
            const float* qp = g_q + base + (long)(it * 64) * HB;
#pragma unroll
            for (int k = 0; k < 8; k++) {
                int c0 = k * 8 + tig;
                aq[k][0] = f2tf(qp[lr0 * HB + c0] * QSC);
                aq[k][1] = f2tf(qp[lr1 * HB + c0] * QSC);
                aq[k][2] = f2tf(qp[lr0 * HB + c0 + 4] * QSC);
                aq[k][3] = f2tf(qp[lr1 * HB + c0 + 4] * QSC);
            }
        }

        float l0 = 0.f, l1 = 0.f;
        float acc[4][4];
#pragma unroll
        for (int nt = 0; nt < 4; nt++)
#pragma unroll
            for (int c = 0; c < 4; c++) acc[nt][c] = 0.f;

        if (cnt >= 1) ATTN_ISSUE(j0, 0);
        if (cnt >= 2) ATTN_ISSUE(j0 + 1, 1);

        for (int jt = j0; jt <= j1; jt++) {
            const int cur = (jt - j0) & 1;
            if (jt < j1)
                asm volatile("cp.async.wait_group 1;" ::: "memory");
            else
                asm volatile("cp.async.wait_group 0;" ::: "memory");
            __syncthreads();   // tile jt visible to all threads

            const uint32_t* ksb = sm + (cur ? KS1_OFF : KS0_OFF);
            const uint32_t* vsb = sm + (cur ? VS1_OFF : VS0_OFF);

            // ---- S' = (Q*QSC) K^T : 16x32 per warp (log2-domain) ----
            float sfr[4][4];
#pragma unroll
            for (int nt = 0; nt < 4; nt++)
#pragma unroll
                for (int c = 0; c < 4; c++) sfr[nt][c] = 0.f;

#pragma unroll
            for (int nt = 0; nt < 4; nt++) {
                const uint32_t* krow = &ksb[(32 * wc + 8 * nt + g) * KS_STR];
#pragma unroll
                for (int k = 0; k < 8; k++) {
                    uint32_t b0 = krow[8 * k + tig];
                    uint32_t b1 = krow[8 * k + tig + 4];
                    mma8(sfr[nt], aq[k], b0, b1);
                }
            }

            // ---- causal mask (diagonal tile only) ----
            if (jt == it) {
#pragma unroll
                for (int nt = 0; nt < 4; nt++) {
                    int c0 = 32 * wc + 8 * nt + 2 * tig;
#pragma unroll
                    for (int c = 0; c < 4; c++) {
                        int lc = c0 + (c & 1);
                        int lr = (c < 2) ? lr0 : lr1;
                        if (lc > lr) sfr[nt][c] = -1e30f;
                    }
                }
            }

            // ---- p = 2^s' (fixed-shift softmax), stage P ----
#pragma unroll
            for (int nt = 0; nt < 4; nt++) {
                float e0 = exp2f(sfr[nt][0]);
                float e1 = exp2f(sfr[nt][1]);
                float e2 = exp2f(sfr[nt][2]);
                float e3 = exp2f(sfr[nt][3]);
                l0 += e0 + e1;
                l1 += e2 + e3;
                int col = 32 * wc + 8 * nt + 2 * tig;
                *(uint2*)&ps[lr0 * PS_STR + col] = make_uint2(f2tf(e0), f2tf(e1));
                *(uint2*)&ps[lr1 * PS_STR + col] = make_uint2(f2tf(e2), f2tf(e3));
            }
            // pair barrier: warps (wr,0),(wr,1) share ps rows
            asm volatile("bar.sync %0, 64;" :: "r"(1 + wr));

            // ---- O += P V : 16x32 per warp ----
#pragma unroll
            for (int k = 0; k < 8; k++) {
                uint32_t ap[4];
                ap[0] = ps[lr0 * PS_STR + 8 * k + tig];
                ap[1] = ps[lr1 * PS_STR + 8 * k + tig];
                ap[2] = ps[lr0 * PS_STR + 8 * k + tig + 4];
                ap[3] = ps[lr1 * PS_STR + 8 * k + tig + 4];
                const uint32_t* v0 = &vsb[(8 * k + tig) * VS_STR + 32 * wc];
                const uint32_t* v1 = &vsb[(8 * k + tig + 4) * VS_STR + 32 * wc];
#pragma unroll
                for (int nt = 0; nt < 4; nt++)
                    mma8(acc[nt], ap, v0[8 * nt + g], v1[8 * nt + g]);
            }

            __syncthreads();   // all warps done with buf[cur] and ps
            if (jt + 2 <= j1) ATTN_ISSUE(jt + 2, cur);
        }

        // ---- reduce partial row sums; write partials to scratch ----
        l0 += __shfl_xor_sync(0xffffffffu, l0, 1);
        l0 += __shfl_xor_sync(0xffffffffu, l0, 2);
        l1 += __shfl_xor_sync(0xffffffffu, l1, 1);
        l1 += __shfl_xor_sync(0xffffffffu, l1, 2);
        if (tig == 0) {
            reds[wc * 64 + lr0] = l0;
            reds[wc * 64 + lr1] = l1;
        }
        __syncthreads();

        const long pidx = ((long)(b * 64 + it) * 2 + z);
        if (tig == 0 && wc == 0) {
            g_pl[pidx * 64 + lr0] = reds[lr0] + reds[64 + lr0];
            g_pl[pidx * 64 + lr1] = reds[lr1] + reds[64 + lr1];
        }
        float* pa = g_pacc + pidx * 64 * 64;
#pragma unroll
        for (int nt = 0; nt < 4; nt++) {
            int col = 32 * wc + 8 * nt + 2 * tig;
            *(float2*)&pa[lr0 * 64 + col] = make_float2(acc[nt][0], acc[nt][1]);
            *(float2*)&pa[lr1 * 64 + col] = make_float2(acc[nt][2], acc[nt][3]);
        }
        __syncthreads();  // reds reuse safety for next half
    }
}

// ---------------------------------------------------------------------------
// Kernel 3: combine split-K partials.  out = (acc_z0 + acc_z1) / (l_z0+l_z1)
// Grid (64, 4), 256 threads: one block per (it, b) Q tile.
// ---------------------------------------------------------------------------
__global__ __launch_bounds__(256) void combine_kernel(float* __restrict__ out)
{
    const int it = blockIdx.x, b = blockIdx.y;
    const int tid = threadIdx.x;
    const long pidx = (long)(b * 64 + it) * 2;
    const float* pa0 = g_pacc + pidx * 64 * 64;
    const float* pa1 = pa0 + 64 * 64;
    const float* pl0 = g_pl + pidx * 64;
    const float* pl1 = pl0 + 64;

    __shared__ float linv[64];
    if (tid < 64) linv[tid] = 1.f / (pl0[tid] + pl1[tid]);
    __syncthreads();

    float* op = out + ((long)b * TB + (long)it * 64) * HB;
#pragma unroll
    for (int i = 0; i < 4; i++) {
        int f = tid + 256 * i;
        int r = f >> 4, c = (f & 15) * 4;
        float4 a0 = *(const float4*)&pa0[r * 64 + c];
        float4 a1 = *(const float4*)&pa1[r * 64 + c];
        float s = linv[r];
        *(float4*)&op[r * HB + c] =
            make_float4((a0.x + a1.x) * s, (a0.y + a1.y) * s,
                        (a0.z + a1.z) * s, (a0.w + a1.w) * s);
    }
}

extern "C" void kernel_launch(void* const* d_in, const int* in_sizes, int n_in,
                              void* d_out, int out_size)
{
    const float* x  = (const float*)d_in[0];
    const float* Wk = (const float*)d_in[1];
    const float* bk = (const float*)d_in[2];
    const float* Wq = (const float*)d_in[3];
    const float* bq = (const float*)d_in[4];
    const float* Wv = (const float*)d_in[5];
    const float* bv = (const float*)d_in[6];
    float* out = (float*)d_out;

    (void)in_sizes; (void)n_in; (void)out_size;

    static bool attr_done = false;
    if (!attr_done) {
        cudaFuncSetAttribute(attn_kernel,
                             cudaFuncAttributeMaxDynamicSharedMemorySize,
                             ATTN_SMEM);
        cudaFuncSetAttribute(qkv_kernel,
                             cudaFuncAttributeMaxDynamicSharedMemorySize,
                             QKV_SMEM);
        attr_done = true;
    }

    qkv_kernel<<<256, 256, QKV_SMEM>>>(x, Wk, bk, Wq, bq, Wv, bv);
    attn_kernel<<<dim3(32, 4, 2), 256, ATTN_SMEM>>>();
    combine_kernel<<<dim3(64, 4), 256>>>(out);
}